// round 1
// baseline (speedup 1.0000x reference)
#include <cuda_runtime.h>
#include <cuda_bf16.h>
#include <math.h>

// ---------------- problem constants ----------------
#define B_  2
#define L_  4096
#define D_  512
#define H_  8
#define DH_ 64
#define BL_ (B_ * L_)          // 8192
#define FF_ 2048               // 4*D

// ---------------- scratch (static device globals; no allocation) ----------------
__device__ float g_xn [BL_ * D_];
__device__ float g_q  [B_ * H_ * L_ * DH_];
__device__ float g_k  [B_ * H_ * L_ * DH_];
__device__ float g_v  [B_ * H_ * L_ * DH_];
__device__ float g_att[BL_ * D_];
__device__ float g_x1 [BL_ * D_];
__device__ float g_h  [BL_ * D_];
__device__ float g_ff [BL_ * FF_];

// ============================================================
// LayerNorm: one block per row of 512
// ============================================================
__global__ __launch_bounds__(256) void ln_kernel(const float* __restrict__ x,
                                                 const float* __restrict__ g,
                                                 const float* __restrict__ b,
                                                 float* __restrict__ y) {
    int row = blockIdx.x;
    const float* xr = x + (size_t)row * D_;
    float* yr = y + (size_t)row * D_;
    int tid = threadIdx.x;

    float v0 = xr[tid];
    float v1 = xr[tid + 256];
    float s  = v0 + v1;
    float ss = v0 * v0 + v1 * v1;

    #pragma unroll
    for (int o = 16; o > 0; o >>= 1) {
        s  += __shfl_xor_sync(0xffffffffu, s,  o);
        ss += __shfl_xor_sync(0xffffffffu, ss, o);
    }
    __shared__ float red[16];
    int w = tid >> 5, lane = tid & 31;
    if (lane == 0) { red[w] = s; red[w + 8] = ss; }
    __syncthreads();
    float S = 0.f, SS = 0.f;
    #pragma unroll
    for (int i = 0; i < 8; i++) { S += red[i]; SS += red[i + 8]; }
    float mu  = S * (1.0f / D_);
    float var = SS * (1.0f / D_) - mu * mu;
    float inv = rsqrtf(var + 1e-5f);

    yr[tid]       = (v0 - mu) * inv * g[tid]       + b[tid];
    yr[tid + 256] = (v1 - mu) * inv * g[tid + 256] + b[tid + 256];
}

// ============================================================
// GEMM: C[M,N] = A[M,K] @ B[N,K]^T, 128x128x16 tiles, 256 threads, 8x8 micro
// epilogue modes: 0 = qkv scatter, 1 = residual add, 2 = SiLU
// ============================================================
#define GEMM_MODE_QKV   0
#define GEMM_MODE_RESID 1
#define GEMM_MODE_SILU  2

__global__ __launch_bounds__(256) void gemm_kernel(
    const float* __restrict__ A, const float* __restrict__ B,
    int M, int N, int K, int mode,
    const float* __restrict__ resid, float* __restrict__ out,
    float* __restrict__ oq, float* __restrict__ ok, float* __restrict__ ov)
{
    __shared__ float As[16][132];
    __shared__ float Bs[16][132];

    int bm = blockIdx.y, bn = blockIdx.x;
    int tid = threadIdx.x;
    int tm = tid >> 4, tn = tid & 15;

    const float* Ab = A + (size_t)bm * 128 * K;
    const float* Bb = B + (size_t)bn * 128 * K;

    int lrow = tid >> 2;            // 0..63
    int lcol = (tid & 3) << 2;      // 0,4,8,12

    float acc[8][8];
    #pragma unroll
    for (int i = 0; i < 8; i++)
        #pragma unroll
        for (int j = 0; j < 8; j++) acc[i][j] = 0.f;

    for (int k0 = 0; k0 < K; k0 += 16) {
        #pragma unroll
        for (int p = 0; p < 2; p++) {
            int row = lrow + p * 64;
            float4 av = *(const float4*)&Ab[(size_t)row * K + k0 + lcol];
            As[lcol + 0][row] = av.x; As[lcol + 1][row] = av.y;
            As[lcol + 2][row] = av.z; As[lcol + 3][row] = av.w;
            float4 bv = *(const float4*)&Bb[(size_t)row * K + k0 + lcol];
            Bs[lcol + 0][row] = bv.x; Bs[lcol + 1][row] = bv.y;
            Bs[lcol + 2][row] = bv.z; Bs[lcol + 3][row] = bv.w;
        }
        __syncthreads();
        #pragma unroll
        for (int kk = 0; kk < 16; kk++) {
            float4 a0 = *(const float4*)&As[kk][tm * 8];
            float4 a1 = *(const float4*)&As[kk][tm * 8 + 4];
            float4 b0 = *(const float4*)&Bs[kk][tn * 8];
            float4 b1 = *(const float4*)&Bs[kk][tn * 8 + 4];
            float a[8] = {a0.x, a0.y, a0.z, a0.w, a1.x, a1.y, a1.z, a1.w};
            float bb[8] = {b0.x, b0.y, b0.z, b0.w, b1.x, b1.y, b1.z, b1.w};
            #pragma unroll
            for (int i = 0; i < 8; i++)
                #pragma unroll
                for (int j = 0; j < 8; j++)
                    acc[i][j] = fmaf(a[i], bb[j], acc[i][j]);
        }
        __syncthreads();
    }

    // epilogue
    #pragma unroll
    for (int i = 0; i < 8; i++) {
        int gm = bm * 128 + tm * 8 + i;
        #pragma unroll
        for (int j = 0; j < 8; j++) {
            int gn = bn * 128 + tn * 8 + j;
            float val = acc[i][j];
            if (mode == GEMM_MODE_QKV) {
                int which = gn >> 9;
                int h = (gn >> 6) & 7;
                int d = gn & 63;
                int bb_ = gm >> 12;      // gm / 4096
                int l  = gm & 4095;
                float* dst = (which == 0) ? oq : (which == 1) ? ok : ov;
                dst[(((size_t)bb_ * H_ + h) * L_ + l) * DH_ + d] = val;
            } else if (mode == GEMM_MODE_RESID) {
                size_t idx = (size_t)gm * N + gn;
                out[idx] = resid[idx] + val;
            } else { // SILU
                size_t idx = (size_t)gm * N + gn;
                out[idx] = val / (1.0f + __expf(-val));
            }
        }
    }
}

// ============================================================
// Flash attention (fp32), 64-query x 64-key tiles, online softmax,
// temporal decay bias + causal mask + key padding mask.
// grid: (L/64, B*H), 256 threads.
// ============================================================
#define PAD 68
__global__ __launch_bounds__(256) void attn_kernel(
    const float* __restrict__ q, const float* __restrict__ k,
    const float* __restrict__ v, const float* __restrict__ ts,
    const float* __restrict__ mask, const float* __restrict__ decay_rate,
    float* __restrict__ out)
{
    extern __shared__ float sm[];
    float* sQt = sm;                 // [64][PAD]  (d-major: sQt[d][r])
    float* sKt = sQt + 64 * PAD;     // [64][PAD]  (d-major: sKt[d][c])
    float* sV  = sKt + 64 * PAD;     // [64][PAD]  (sV[c][e])
    float* sSt = sV  + 64 * PAD;     // [64][PAD]  (sSt[c][r])
    float* tq   = sSt + 64 * PAD;    // [64]
    float* tk   = tq + 64;
    float* km   = tk + 64;
    float* mrow = km + 64;
    float* lrow = mrow + 64;
    float* frow = lrow + 64;

    int qt = blockIdx.x;
    int bh = blockIdx.y;
    int b  = bh >> 3, h = bh & 7;
    int tid = threadIdx.x;
    int tm = tid >> 4, tn = tid & 15;

    const float* qbase = q + ((size_t)bh * L_ + qt * 64) * DH_;

    // Q tile, transposed into smem
    for (int i = tid; i < 64 * 64; i += 256) {
        int r = i >> 6, d = i & 63;
        sQt[d * PAD + r] = qbase[i];
    }
    if (tid < 64) {
        int qi = qt * 64 + tid;
        tq[tid]   = ts[b * L_ + qi];
        mrow[tid] = -1e30f;
        lrow[tid] = 0.f;
    }
    float dcy = log1pf(__expf(decay_rate[h]));
    const float scale = 0.125f;       // 1/sqrt(64)
    float acc[4][4];
    #pragma unroll
    for (int i = 0; i < 4; i++)
        #pragma unroll
        for (int j = 0; j < 4; j++) acc[i][j] = 0.f;
    __syncthreads();

    for (int jt = 0; jt <= qt; jt++) {
        const float* kbase = k + ((size_t)bh * L_ + jt * 64) * DH_;
        const float* vbase = v + ((size_t)bh * L_ + jt * 64) * DH_;
        for (int i = tid; i < 64 * 64; i += 256) {
            int c = i >> 6, d = i & 63;
            sKt[d * PAD + c] = kbase[i];
            sV[c * PAD + d]  = vbase[i];
        }
        if (tid < 64) {
            int kj = jt * 64 + tid;
            tk[tid] = ts[b * L_ + kj];
            km[tid] = mask[b * L_ + kj];
        }
        __syncthreads();

        // ---- S = Q K^T (4x4 per thread) ----
        float s[4][4];
        #pragma unroll
        for (int i = 0; i < 4; i++)
            #pragma unroll
            for (int j = 0; j < 4; j++) s[i][j] = 0.f;
        #pragma unroll 4
        for (int d = 0; d < 64; d++) {
            float4 q4 = *(const float4*)(sQt + d * PAD + (tm << 2));
            float4 k4 = *(const float4*)(sKt + d * PAD + (tn << 2));
            float a[4] = {q4.x, q4.y, q4.z, q4.w};
            float bb[4] = {k4.x, k4.y, k4.z, k4.w};
            #pragma unroll
            for (int i = 0; i < 4; i++)
                #pragma unroll
                for (int j = 0; j < 4; j++)
                    s[i][j] = fmaf(a[i], bb[j], s[i][j]);
        }

        // bias + masks, store transposed (sSt[c][r])
        #pragma unroll
        for (int i = 0; i < 4; i++) {
            int r = tm * 4 + i;
            int qi = qt * 64 + r;
            #pragma unroll
            for (int j = 0; j < 4; j++) {
                int c = tn * 4 + j;
                int kj = jt * 64 + c;
                float val = s[i][j] * scale
                          - dcy * fabsf(tq[r] - tk[c]) * (1.0f / 24.0f);
                if (kj > qi || km[c] == 0.f) val = -1e30f;
                sSt[c * PAD + r] = val;
            }
        }
        __syncthreads();

        // ---- online softmax: thread t < 64 owns row t ----
        if (tid < 64) {
            int r = tid;
            float tmax = -1e30f;
            #pragma unroll 8
            for (int c = 0; c < 64; c++) tmax = fmaxf(tmax, sSt[c * PAD + r]);
            float mold = mrow[r];
            float mnew = fmaxf(mold, tmax);
            float fac  = __expf(mold - mnew);   // mold==mnew==-1e30 -> 1, acc is 0, safe
            float sum  = 0.f;
            #pragma unroll 8
            for (int c = 0; c < 64; c++) {
                float sv = sSt[c * PAD + r];
                float p = (sv <= -1e29f) ? 0.f : __expf(sv - mnew);
                sSt[c * PAD + r] = p;
                sum += p;
            }
            lrow[r] = lrow[r] * fac + sum;
            mrow[r] = mnew;
            frow[r] = fac;
        }
        __syncthreads();

        // ---- O = O*fac + P V ----
        #pragma unroll
        for (int i = 0; i < 4; i++) {
            float f = frow[tm * 4 + i];
            #pragma unroll
            for (int j = 0; j < 4; j++) acc[i][j] *= f;
        }
        #pragma unroll 4
        for (int c = 0; c < 64; c++) {
            float4 p4 = *(const float4*)(sSt + c * PAD + (tm << 2));
            float4 v4 = *(const float4*)(sV  + c * PAD + (tn << 2));
            float p[4] = {p4.x, p4.y, p4.z, p4.w};
            float vv[4] = {v4.x, v4.y, v4.z, v4.w};
            #pragma unroll
            for (int i = 0; i < 4; i++)
                #pragma unroll
                for (int j = 0; j < 4; j++)
                    acc[i][j] = fmaf(p[i], vv[j], acc[i][j]);
        }
        __syncthreads();   // protect smem before next tile's loads
    }

    // ---- write out: [B, L, H*dh] ----
    #pragma unroll
    for (int i = 0; i < 4; i++) {
        int r = tm * 4 + i;
        int qi = qt * 64 + r;
        float inv = 1.0f / lrow[r];
        float4 o;
        o.x = acc[i][0] * inv; o.y = acc[i][1] * inv;
        o.z = acc[i][2] * inv; o.w = acc[i][3] * inv;
        *(float4*)&out[((size_t)b * L_ + qi) * D_ + h * DH_ + tn * 4] = o;
    }
}

// ============================================================
// launch
// ============================================================
extern "C" void kernel_launch(void* const* d_in, const int* in_sizes, int n_in,
                              void* d_out, int out_size) {
    const float* x      = (const float*)d_in[0];
    const float* tsb    = (const float*)d_in[1];
    const float* mask   = (const float*)d_in[2];
    const float* ln1_g  = (const float*)d_in[3];
    const float* ln1_b  = (const float*)d_in[4];
    const float* w_qkv  = (const float*)d_in[5];
    const float* w_out  = (const float*)d_in[6];
    const float* decay  = (const float*)d_in[7];
    const float* ln2_g  = (const float*)d_in[8];
    const float* ln2_b  = (const float*)d_in[9];
    const float* w_ff1  = (const float*)d_in[10];
    const float* w_ff2  = (const float*)d_in[11];
    float* out = (float*)d_out;

    float *xn, *q, *k, *v, *att, *x1, *hh, *ff;
    cudaGetSymbolAddress((void**)&xn,  g_xn);
    cudaGetSymbolAddress((void**)&q,   g_q);
    cudaGetSymbolAddress((void**)&k,   g_k);
    cudaGetSymbolAddress((void**)&v,   g_v);
    cudaGetSymbolAddress((void**)&att, g_att);
    cudaGetSymbolAddress((void**)&x1,  g_x1);
    cudaGetSymbolAddress((void**)&hh,  g_h);
    cudaGetSymbolAddress((void**)&ff,  g_ff);

    int attn_smem = (4 * 64 * PAD + 6 * 64) * sizeof(float);   // ~71 KB
    cudaFuncSetAttribute(attn_kernel, cudaFuncAttributeMaxDynamicSharedMemorySize, attn_smem);

    // 1) LN1
    ln_kernel<<<BL_, 256>>>(x, ln1_g, ln1_b, xn);

    // 2) QKV GEMM: [8192,512] @ [1536,512]^T
    gemm_kernel<<<dim3(1536 / 128, BL_ / 128), 256>>>(
        xn, w_qkv, BL_, 1536, D_, GEMM_MODE_QKV, nullptr, nullptr, q, k, v);

    // 3) attention
    attn_kernel<<<dim3(L_ / 64, B_ * H_), 256, attn_smem>>>(
        q, k, v, tsb, mask, decay, att);

    // 4) out-proj + residual: x1 = x + att @ w_out^T
    gemm_kernel<<<dim3(D_ / 128, BL_ / 128), 256>>>(
        att, w_out, BL_, D_, D_, GEMM_MODE_RESID, x, x1, nullptr, nullptr, nullptr);

    // 5) LN2
    ln_kernel<<<BL_, 256>>>(x1, ln2_g, ln2_b, hh);

    // 6) FF1 + SiLU
    gemm_kernel<<<dim3(FF_ / 128, BL_ / 128), 256>>>(
        hh, w_ff1, BL_, FF_, D_, GEMM_MODE_SILU, nullptr, ff, nullptr, nullptr, nullptr);

    // 7) FF2 + residual -> d_out
    gemm_kernel<<<dim3(D_ / 128, BL_ / 128), 256>>>(
        ff, w_ff2, BL_, D_, FF_, GEMM_MODE_RESID, x1, out, nullptr, nullptr, nullptr);
}